// round 6
// baseline (speedup 1.0000x reference)
#include <cuda_runtime.h>
#include <cuda_bf16.h>
#include <math_constants.h>
#include <cstdint>

#define NQ        256
#define NK        50000
#define DD        64
#define KT        128
#define NKT       391          // ceil(50000/128)
#define NKPAD     (NKT * KT)   // 50048
#define NHALF     782
#define NHP       784
#define OBS_ELEMS 3072
#define CAP       64
#define MARGIN    0.05f        // >> 2x split-bf16 score error bound

// ---- static device scratch ----
__device__ __nv_bfloat16 g_khi[NKPAD * DD];
__device__ __nv_bfloat16 g_klo[NKPAD * DD];
__device__ __nv_bfloat16 g_qhi[NQ * DD];
__device__ __nv_bfloat16 g_qlo[NQ * DD];
__device__ float g_ksq[NKPAD];
__device__ float g_hmin[NQ * NHP];
__device__ int   g_candlist[NQ * CAP];
__device__ int   g_candcnt[NQ];
__device__ int   g_topidx[NQ * 8];

// ---- kernel-1 smem (bytes): 4 tiles 128x72 bf16 + ksq ----
#define TSTRIDE_B  144
#define SM_QHI 0
#define SM_QLO 18432
#define SM_KHI 36864
#define SM_KLO 55296
#define SM_KSQ 73728
#define SM_TOTAL 74240

// ============================ helpers ============================
__device__ __forceinline__ uint32_t smem_u32(const void* p) {
    uint32_t a;
    asm("{ .reg .u64 t; cvta.to.shared.u64 t, %1; cvt.u32.u64 %0, t; }" : "=r"(a) : "l"(p));
    return a;
}
__device__ __forceinline__ void ldsm_x4(uint32_t& r0, uint32_t& r1, uint32_t& r2,
                                        uint32_t& r3, uint32_t a) {
    asm volatile("ldmatrix.sync.aligned.m8n8.x4.shared.b16 {%0,%1,%2,%3}, [%4];"
                 : "=r"(r0), "=r"(r1), "=r"(r2), "=r"(r3) : "r"(a));
}
__device__ __forceinline__ void mma_bf16(float& c0, float& c1, float& c2, float& c3,
                                         uint32_t a0, uint32_t a1, uint32_t a2, uint32_t a3,
                                         uint32_t b0, uint32_t b1) {
    asm volatile("mma.sync.aligned.m16n8k16.row.col.f32.bf16.bf16.f32 "
                 "{%0,%1,%2,%3},{%4,%5,%6,%7},{%8,%9},{%0,%1,%2,%3};"
                 : "+f"(c0), "+f"(c1), "+f"(c2), "+f"(c3)
                 : "r"(a0), "r"(a1), "r"(a2), "r"(a3), "r"(b0), "r"(b1));
}

// split 32 floats into hi/lo bf16 (4x uint2 each) + sum of squares
__device__ __forceinline__ void split32(const float4* __restrict__ s,
                                        uint2* __restrict__ ph,
                                        uint2* __restrict__ pl,
                                        float& ss) {
    #pragma unroll
    for (int i = 0; i < 8; i++) {
        float4 v = s[i];
        ss = fmaf(v.x, v.x, ss); ss = fmaf(v.y, v.y, ss);
        ss = fmaf(v.z, v.z, ss); ss = fmaf(v.w, v.w, ss);
        __nv_bfloat16 h0 = __float2bfloat16(v.x), h1 = __float2bfloat16(v.y);
        __nv_bfloat16 h2 = __float2bfloat16(v.z), h3 = __float2bfloat16(v.w);
        __nv_bfloat16 l0 = __float2bfloat16(v.x - __bfloat162float(h0));
        __nv_bfloat16 l1 = __float2bfloat16(v.y - __bfloat162float(h1));
        __nv_bfloat16 l2 = __float2bfloat16(v.z - __bfloat162float(h2));
        __nv_bfloat16 l3 = __float2bfloat16(v.w - __bfloat162float(h3));
        __nv_bfloat162 hh0 = __halves2bfloat162(h0, h1), hh1 = __halves2bfloat162(h2, h3);
        __nv_bfloat162 ll0 = __halves2bfloat162(l0, l1), ll1 = __halves2bfloat162(l2, l3);
        uint2 uh, ul;
        uh.x = *(uint32_t*)&hh0; uh.y = *(uint32_t*)&hh1;
        ul.x = *(uint32_t*)&ll0; ul.y = *(uint32_t*)&ll1;
        ph[i] = uh; pl[i] = ul;
    }
}

#define INS8T(s_, j_)                                                            \
    if ((s_) < l[7] || ((s_) == l[7] && (j_) < li[7])) {                         \
        l[7] = (s_); li[7] = (j_);                                               \
        _Pragma("unroll")                                                        \
        for (int u = 7; u > 0; u--)                                              \
            if (l[u] < l[u-1] || (l[u] == l[u-1] && li[u] < li[u-1])) {          \
                float ts = l[u]; l[u] = l[u-1]; l[u-1] = ts;                     \
                int ti = li[u]; li[u] = li[u-1]; li[u-1] = ti; }                 \
    }

// ======================================================================
// Kernel 0: one-time fp32 -> split-bf16 conversion (k and q) + ksq
// grid 393 x 256 threads. blocks 0..390: k; 391..392: q.
// ======================================================================
__global__ __launch_bounds__(256) void knn_convert(
    const float* __restrict__ qm, const float* __restrict__ km)
{
    const int b = blockIdx.x, tid = threadIdx.x;
    const int row_in_b = tid >> 1, hf = tid & 1;

    if (b < NKT) {
        const int row = b * KT + row_in_b;
        uint2* ph = (uint2*)(g_khi + (size_t)row * DD + hf * 32);
        uint2* pl = (uint2*)(g_klo + (size_t)row * DD + hf * 32);
        float ss = 0.f;
        if (row < NK) {
            split32((const float4*)(km + (size_t)row * DD + hf * 32), ph, pl, ss);
        } else {
            uint2 z = make_uint2(0u, 0u);
            #pragma unroll
            for (int i = 0; i < 8; i++) { ph[i] = z; pl[i] = z; }
        }
        float tot = ss + __shfl_xor_sync(0xFFFFFFFFu, ss, 1);
        if (hf == 0) g_ksq[row] = (row < NK) ? tot : CUDART_INF_F;
    } else {
        const int row = (b - NKT) * 128 + row_in_b;
        uint2* ph = (uint2*)(g_qhi + (size_t)row * DD + hf * 32);
        uint2* pl = (uint2*)(g_qlo + (size_t)row * DD + hf * 32);
        float ss = 0.f;
        split32((const float4*)(qm + (size_t)row * DD + hf * 32), ph, pl, ss);
    }
}

// ======================================================================
// Kernel 1: split-bf16 mma.sync score GEMM -> per-(query,half) MIN
// grid (391, 2), 256 threads (8 warps: 4 m-rows x 2 n-cols)
// ======================================================================
__global__ __launch_bounds__(256) void knn_score_min()
{
    extern __shared__ char smem[];
    const uint32_t sb = smem_u32(smem);
    const int tid  = threadIdx.x;
    const int wid  = tid >> 5;
    const int lane = tid & 31;
    const int k0   = blockIdx.x * KT;
    const int q0   = blockIdx.y * 128;

    float* ksq = (float*)(smem + SM_KSQ);

    // ---- copy pre-split tiles GMEM -> SMEM (no conversion) ----
    {
        const int row = tid >> 1, hf = tid & 1;
        const uint32_t soff = (uint32_t)row * TSTRIDE_B + hf * 64;
        const size_t qoff = (size_t)(q0 + row) * DD + hf * 32;
        const size_t koff = (size_t)(k0 + row) * DD + hf * 32;
        const uint4* sqh = (const uint4*)(g_qhi + qoff);
        const uint4* sql = (const uint4*)(g_qlo + qoff);
        const uint4* skh = (const uint4*)(g_khi + koff);
        const uint4* skl = (const uint4*)(g_klo + koff);
        uint4* dqh = (uint4*)(smem + SM_QHI + soff);
        uint4* dql = (uint4*)(smem + SM_QLO + soff);
        uint4* dkh = (uint4*)(smem + SM_KHI + soff);
        uint4* dkl = (uint4*)(smem + SM_KLO + soff);
        #pragma unroll
        for (int i = 0; i < 4; i++) {
            dqh[i] = sqh[i];
            dql[i] = sql[i];
            dkh[i] = skh[i];
            dkl[i] = skl[i];
        }
        if (tid < 128) ksq[tid] = g_ksq[k0 + tid];
    }
    __syncthreads();

    // ---- warp GEMM: 32(m) x 64(n), 3 split passes ----
    const int mrow = wid >> 1;
    const int ncol = wid & 1;

    float acc[2][8][4];
    #pragma unroll
    for (int mt = 0; mt < 2; mt++)
        #pragma unroll
        for (int nt = 0; nt < 8; nt++)
            #pragma unroll
            for (int c = 0; c < 4; c++) acc[mt][nt][c] = 0.f;

    const uint32_t abase[3] = { sb + SM_QHI, sb + SM_QHI, sb + SM_QLO };
    const uint32_t bbase[3] = { sb + SM_KHI, sb + SM_KLO, sb + SM_KHI };

    #pragma unroll
    for (int pass = 0; pass < 3; pass++) {
        #pragma unroll
        for (int ks16 = 0; ks16 < 4; ks16++) {
            const uint32_t dby = ks16 * 32;
            uint32_t a[2][4];
            #pragma unroll
            for (int mt = 0; mt < 2; mt++) {
                uint32_t addr = abase[pass]
                    + (uint32_t)(mrow * 32 + mt * 16 + (lane & 15)) * TSTRIDE_B
                    + dby + ((lane >> 4) << 4);
                ldsm_x4(a[mt][0], a[mt][1], a[mt][2], a[mt][3], addr);
            }
            uint32_t b[8][2];
            #pragma unroll
            for (int np = 0; np < 4; np++) {
                uint32_t n = (uint32_t)(ncol * 64 + np * 16 + ((lane >> 4) << 3) + (lane & 7));
                uint32_t addr = bbase[pass] + n * TSTRIDE_B + dby + (((lane >> 3) & 1) << 4);
                ldsm_x4(b[np * 2][0], b[np * 2][1], b[np * 2 + 1][0], b[np * 2 + 1][1], addr);
            }
            #pragma unroll
            for (int mt = 0; mt < 2; mt++)
                #pragma unroll
                for (int nt = 0; nt < 8; nt++)
                    mma_bf16(acc[mt][nt][0], acc[mt][nt][1], acc[mt][nt][2], acc[mt][nt][3],
                             a[mt][0], a[mt][1], a[mt][2], a[mt][3],
                             b[nt][0], b[nt][1]);
        }
    }

    // ---- branch-free epilogue: per-row min of (ksq - 2*dot) over 64 cols ----
    {
        const int g = lane >> 2, t = lane & 3;
        float rm[4];
        #pragma unroll
        for (int mt = 0; mt < 2; mt++) {
            float m0 = CUDART_INF_F, m1 = CUDART_INF_F;
            #pragma unroll
            for (int nt = 0; nt < 8; nt++) {
                const int col = ncol * 64 + nt * 8 + t * 2;
                const float kq0 = ksq[col], kq1 = ksq[col + 1];
                m0 = fminf(m0, fminf(fmaf(-2.f, acc[mt][nt][0], kq0),
                                     fmaf(-2.f, acc[mt][nt][1], kq1)));
                m1 = fminf(m1, fminf(fmaf(-2.f, acc[mt][nt][2], kq0),
                                     fmaf(-2.f, acc[mt][nt][3], kq1)));
            }
            rm[mt * 2] = m0; rm[mt * 2 + 1] = m1;
        }
        #pragma unroll
        for (int r = 0; r < 4; r++) {
            rm[r] = fminf(rm[r], __shfl_xor_sync(0xFFFFFFFFu, rm[r], 1));
            rm[r] = fminf(rm[r], __shfl_xor_sync(0xFFFFFFFFu, rm[r], 2));
        }
        if (t == 0) {
            const int half = blockIdx.x * 2 + ncol;
            const int rowb = q0 + mrow * 32 + g;
            g_hmin[(size_t)(rowb)      * NHP + half] = rm[0];
            g_hmin[(size_t)(rowb + 8)  * NHP + half] = rm[1];
            g_hmin[(size_t)(rowb + 16) * NHP + half] = rm[2];
            g_hmin[(size_t)(rowb + 24) * NHP + half] = rm[3];
        }
    }
}

// ======================================================================
// Kernel 2: per-query 8th-smallest half-min -> cutoff -> compact halves
// ======================================================================
__global__ __launch_bounds__(256) void knn_threshold()
{
    __shared__ float ms[256 * 8];
    __shared__ float s_cut;
    __shared__ int   s_cnt;
    const int q = blockIdx.x, tid = threadIdx.x;

    float l[8];
    #pragma unroll
    for (int i = 0; i < 8; i++) l[i] = CUDART_INF_F;

    #pragma unroll
    for (int r = 0; r < 4; r++) {
        const int h = tid + r * 256;
        if (h < NHALF) {
            float s = g_hmin[(size_t)q * NHP + h];
            if (s < l[7]) {
                l[7] = s;
                #pragma unroll
                for (int u = 7; u > 0; u--)
                    if (l[u] < l[u-1]) { float ts = l[u]; l[u] = l[u-1]; l[u-1] = ts; }
            }
        }
    }
    #pragma unroll
    for (int m = 0; m < 8; m++) ms[tid * 8 + m] = l[m];

    for (int st = 128; st >= 1; st >>= 1) {
        __syncthreads();
        if (tid < st) {
            const int o = (tid + st) * 8;
            #pragma unroll 1
            for (int m = 0; m < 8; m++) {
                float s = ms[o + m];
                if (s >= l[7]) break;
                l[7] = s;
                #pragma unroll
                for (int u = 7; u > 0; u--)
                    if (l[u] < l[u-1]) { float ts = l[u]; l[u] = l[u-1]; l[u-1] = ts; }
            }
            #pragma unroll
            for (int m = 0; m < 8; m++) ms[tid * 8 + m] = l[m];
        }
    }
    if (tid == 0) { s_cut = l[7] + MARGIN; s_cnt = 0; }
    __syncthreads();

    const float cut = s_cut;
    #pragma unroll
    for (int r = 0; r < 4; r++) {
        const int h = tid + r * 256;
        if (h < NHALF && g_hmin[(size_t)q * NHP + h] <= cut) {
            int p = atomicAdd(&s_cnt, 1);
            if (p < CAP) g_candlist[q * CAP + p] = h;
        }
    }
    __syncthreads();
    if (tid == 0) g_candcnt[q] = (s_cnt < CAP) ? s_cnt : CAP;
}

// ======================================================================
// Kernel 3: exact fp32 rescore of candidate halves -> exact top-8
// ======================================================================
__global__ __launch_bounds__(256) void knn_rescore(
    const float* __restrict__ qm, const float* __restrict__ km)
{
    __shared__ float qs[64];
    __shared__ float ms[256 * 8];
    __shared__ int   mi[256 * 8];
    const int q = blockIdx.x, tid = threadIdx.x;

    if (tid < 64) qs[tid] = qm[(size_t)q * DD + tid];
    __syncthreads();

    const int cnt = g_candcnt[q];
    float l[8]; int li[8];
    #pragma unroll
    for (int i = 0; i < 8; i++) { l[i] = CUDART_INF_F; li[i] = 0x7FFFFFFF; }

    const float4* qp = (const float4*)qs;
    for (int i = tid >> 6; i < cnt; i += 4) {
        const int j = g_candlist[q * CAP + i] * 64 + (tid & 63);
        if (j < NK) {
            const float4* kp = (const float4*)(km + (size_t)j * DD);
            float dot = 0.f, ks = 0.f;
            #pragma unroll
            for (int w = 0; w < 16; w++) {
                float4 kv = kp[w];
                float4 qv = qp[w];
                dot = fmaf(kv.x, qv.x, dot); ks = fmaf(kv.x, kv.x, ks);
                dot = fmaf(kv.y, qv.y, dot); ks = fmaf(kv.y, kv.y, ks);
                dot = fmaf(kv.z, qv.z, dot); ks = fmaf(kv.z, kv.z, ks);
                dot = fmaf(kv.w, qv.w, dot); ks = fmaf(kv.w, kv.w, ks);
            }
            float s = fmaf(-2.f, dot, ks);
            INS8T(s, j);
        }
    }
    #pragma unroll
    for (int m = 0; m < 8; m++) { ms[tid * 8 + m] = l[m]; mi[tid * 8 + m] = li[m]; }

    for (int st = 128; st >= 1; st >>= 1) {
        __syncthreads();
        if (tid < st) {
            const int o = (tid + st) * 8;
            #pragma unroll 1
            for (int m = 0; m < 8; m++) {
                float s = ms[o + m];
                int   j = mi[o + m];
                bool better = (s < l[7]) || (s == l[7] && j < li[7]);
                if (!better) break;
                l[7] = s; li[7] = j;
                #pragma unroll
                for (int u = 7; u > 0; u--)
                    if (l[u] < l[u-1] || (l[u] == l[u-1] && li[u] < li[u-1])) {
                        float ts = l[u]; l[u] = l[u-1]; l[u-1] = ts;
                        int ti = li[u]; li[u] = li[u-1]; li[u-1] = ti;
                    }
            }
            #pragma unroll
            for (int m = 0; m < 8; m++) { ms[tid * 8 + m] = l[m]; mi[tid * 8 + m] = li[m]; }
        }
    }
    if (tid == 0) {
        #pragma unroll
        for (int m = 0; m < 8; m++) g_topidx[q * 8 + m] = li[m];
    }
}

// ======================================================================
// Kernel 4: gather obs[idx] -> out [8, 256, 3072]
// ======================================================================
__global__ __launch_bounds__(256) void knn_gather_kernel(
    const float* __restrict__ obs, float* __restrict__ out)
{
    const int b  = blockIdx.x;
    const int kk = b >> 8;
    const int q  = b & 255;
    const int src = g_topidx[q * 8 + kk];

    const float4* s = (const float4*)(obs + (size_t)src * OBS_ELEMS);
    float4*       d = (float4*)(out + ((size_t)kk * NQ + q) * OBS_ELEMS);

    #pragma unroll
    for (int i = threadIdx.x; i < OBS_ELEMS / 4; i += 256)
        d[i] = s[i];
}

// ======================================================================
extern "C" void kernel_launch(void* const* d_in, const int* in_sizes, int n_in,
                              void* d_out, int out_size)
{
    const float* q   = (const float*)d_in[0];
    const float* k   = (const float*)d_in[1];
    const float* obs = (const float*)d_in[2];
    float* out = (float*)d_out;

    cudaFuncSetAttribute(knn_score_min,
                         cudaFuncAttributeMaxDynamicSharedMemorySize, SM_TOTAL);

    knn_convert<<<NKT + 2, 256>>>(q, k);
    knn_score_min<<<dim3(NKT, 2), 256, SM_TOTAL>>>();
    knn_threshold<<<NQ, 256>>>();
    knn_rescore<<<NQ, 256>>>(q, k);
    knn_gather_kernel<<<NQ * 8, 256>>>(obs, out);
}

// round 7
// speedup vs baseline: 1.0329x; 1.0329x over previous
#include <cuda_runtime.h>
#include <cuda_bf16.h>
#include <math_constants.h>
#include <cstdint>

#define NQ        256
#define NK        50000
#define DD        64
#define KT        128
#define NKT       391          // ceil(50000/128)
#define NHALF     782
#define NHP       784
#define OBS_ELEMS 3072
#define CAP       96
#define MARGIN    2.0f         // >> 2x single-bf16 score error bound

// ---- static device scratch ----
__device__ float g_hmin[NQ * NHP];
__device__ int   g_topidx[NQ * 8];

// ---- kernel-1 smem (bytes): 2 tiles 128x72 bf16 + ksq ----
#define TSTRIDE_B  144
#define SM_Q   0
#define SM_K   18432
#define SM_KSQ 36864
#define SM_TOTAL 37376

// ============================ helpers ============================
__device__ __forceinline__ uint32_t smem_u32(const void* p) {
    uint32_t a;
    asm("{ .reg .u64 t; cvta.to.shared.u64 t, %1; cvt.u32.u64 %0, t; }" : "=r"(a) : "l"(p));
    return a;
}
__device__ __forceinline__ void ldsm_x4(uint32_t& r0, uint32_t& r1, uint32_t& r2,
                                        uint32_t& r3, uint32_t a) {
    asm volatile("ldmatrix.sync.aligned.m8n8.x4.shared.b16 {%0,%1,%2,%3}, [%4];"
                 : "=r"(r0), "=r"(r1), "=r"(r2), "=r"(r3) : "r"(a));
}
__device__ __forceinline__ void mma_bf16(float& c0, float& c1, float& c2, float& c3,
                                         uint32_t a0, uint32_t a1, uint32_t a2, uint32_t a3,
                                         uint32_t b0, uint32_t b1) {
    asm volatile("mma.sync.aligned.m16n8k16.row.col.f32.bf16.bf16.f32 "
                 "{%0,%1,%2,%3},{%4,%5,%6,%7},{%8,%9},{%0,%1,%2,%3};"
                 : "+f"(c0), "+f"(c1), "+f"(c2), "+f"(c3)
                 : "r"(a0), "r"(a1), "r"(a2), "r"(a3), "r"(b0), "r"(b1));
}

// convert 32 floats -> bf16 row chunk, accumulate sum of squares
__device__ __forceinline__ void cvt_row_bf16(char* dst, const float4* __restrict__ s,
                                             float& ss) {
    uint2* d = (uint2*)dst;
    #pragma unroll
    for (int i = 0; i < 8; i++) {
        float4 v = s[i];
        ss = fmaf(v.x, v.x, ss); ss = fmaf(v.y, v.y, ss);
        ss = fmaf(v.z, v.z, ss); ss = fmaf(v.w, v.w, ss);
        __nv_bfloat162 p0 = __floats2bfloat162_rn(v.x, v.y);
        __nv_bfloat162 p1 = __floats2bfloat162_rn(v.z, v.w);
        uint2 u;
        u.x = *(uint32_t*)&p0;
        u.y = *(uint32_t*)&p1;
        d[i] = u;
    }
}

// ======================================================================
// Kernel 1: bf16 mma.sync score GEMM (single pass) -> per-(query,half) MIN
// grid (391, 2), 256 threads (8 warps: 4 m-rows x 2 n-cols)
// ======================================================================
__global__ __launch_bounds__(256) void knn_score_min(
    const float* __restrict__ qm, const float* __restrict__ km)
{
    extern __shared__ char smem[];
    const uint32_t sb = smem_u32(smem);
    const int tid  = threadIdx.x;
    const int wid  = tid >> 5;
    const int lane = tid & 31;
    const int k0   = blockIdx.x * KT;
    const int q0   = blockIdx.y * 128;

    float* ksq = (float*)(smem + SM_KSQ);

    // ---- load + convert q/k tiles, compute ksq ----
    {
        const int row = tid >> 1, hf = tid & 1;
        float dummy = 0.f;
        cvt_row_bf16(smem + SM_Q + row * TSTRIDE_B + hf * 64,
                     (const float4*)(qm + (size_t)(q0 + row) * DD + hf * 32), dummy);
        const int j = k0 + row;
        char* krow = smem + SM_K + row * TSTRIDE_B + hf * 64;
        float ss = 0.f;
        if (j < NK) {
            cvt_row_bf16(krow, (const float4*)(km + (size_t)j * DD + hf * 32), ss);
        } else {
            uint2 z = make_uint2(0u, 0u);
            uint2* d = (uint2*)krow;
            #pragma unroll
            for (int i = 0; i < 8; i++) d[i] = z;
        }
        float tot = ss + __shfl_xor_sync(0xFFFFFFFFu, ss, 1);
        if (hf == 0) ksq[row] = (j < NK) ? tot : CUDART_INF_F;
    }
    __syncthreads();

    // ---- warp GEMM: 32(m) x 64(n), single pass ----
    const int mrow = wid >> 1;
    const int ncol = wid & 1;

    float acc[2][8][4];
    #pragma unroll
    for (int mt = 0; mt < 2; mt++)
        #pragma unroll
        for (int nt = 0; nt < 8; nt++)
            #pragma unroll
            for (int c = 0; c < 4; c++) acc[mt][nt][c] = 0.f;

    #pragma unroll
    for (int ks16 = 0; ks16 < 4; ks16++) {
        const uint32_t dby = ks16 * 32;
        uint32_t a[2][4];
        #pragma unroll
        for (int mt = 0; mt < 2; mt++) {
            uint32_t addr = sb + SM_Q
                + (uint32_t)(mrow * 32 + mt * 16 + (lane & 15)) * TSTRIDE_B
                + dby + ((lane >> 4) << 4);
            ldsm_x4(a[mt][0], a[mt][1], a[mt][2], a[mt][3], addr);
        }
        uint32_t b[8][2];
        #pragma unroll
        for (int np = 0; np < 4; np++) {
            uint32_t n = (uint32_t)(ncol * 64 + np * 16 + ((lane >> 4) << 3) + (lane & 7));
            uint32_t addr = sb + SM_K + n * TSTRIDE_B + dby + (((lane >> 3) & 1) << 4);
            ldsm_x4(b[np * 2][0], b[np * 2][1], b[np * 2 + 1][0], b[np * 2 + 1][1], addr);
        }
        #pragma unroll
        for (int mt = 0; mt < 2; mt++)
            #pragma unroll
            for (int nt = 0; nt < 8; nt++)
                mma_bf16(acc[mt][nt][0], acc[mt][nt][1], acc[mt][nt][2], acc[mt][nt][3],
                         a[mt][0], a[mt][1], a[mt][2], a[mt][3],
                         b[nt][0], b[nt][1]);
    }

    // ---- branch-free epilogue: per-row min of (ksq - 2*dot) over 64 cols ----
    {
        const int g = lane >> 2, t = lane & 3;
        float rm[4];
        #pragma unroll
        for (int mt = 0; mt < 2; mt++) {
            float m0 = CUDART_INF_F, m1 = CUDART_INF_F;
            #pragma unroll
            for (int nt = 0; nt < 8; nt++) {
                const int col = ncol * 64 + nt * 8 + t * 2;
                const float kq0 = ksq[col], kq1 = ksq[col + 1];
                m0 = fminf(m0, fminf(fmaf(-2.f, acc[mt][nt][0], kq0),
                                     fmaf(-2.f, acc[mt][nt][1], kq1)));
                m1 = fminf(m1, fminf(fmaf(-2.f, acc[mt][nt][2], kq0),
                                     fmaf(-2.f, acc[mt][nt][3], kq1)));
            }
            rm[mt * 2] = m0; rm[mt * 2 + 1] = m1;
        }
        #pragma unroll
        for (int r = 0; r < 4; r++) {
            rm[r] = fminf(rm[r], __shfl_xor_sync(0xFFFFFFFFu, rm[r], 1));
            rm[r] = fminf(rm[r], __shfl_xor_sync(0xFFFFFFFFu, rm[r], 2));
        }
        if (t == 0) {
            const int half = blockIdx.x * 2 + ncol;
            const int rowb = q0 + mrow * 32 + g;
            g_hmin[(size_t)(rowb)      * NHP + half] = rm[0];
            g_hmin[(size_t)(rowb + 8)  * NHP + half] = rm[1];
            g_hmin[(size_t)(rowb + 16) * NHP + half] = rm[2];
            g_hmin[(size_t)(rowb + 24) * NHP + half] = rm[3];
        }
    }
}

// ======================================================================
// Kernel 2 (fused): cutoff from half-mins -> compact -> exact fp32
//                   rescore -> exact top-8. grid NQ, 256 threads.
// ======================================================================
#define INS8T(s_, j_)                                                            \
    if ((s_) < l[7] || ((s_) == l[7] && (j_) < li[7])) {                         \
        l[7] = (s_); li[7] = (j_);                                               \
        _Pragma("unroll")                                                        \
        for (int u = 7; u > 0; u--)                                              \
            if (l[u] < l[u-1] || (l[u] == l[u-1] && li[u] < li[u-1])) {          \
                float ts = l[u]; l[u] = l[u-1]; l[u-1] = ts;                     \
                int ti = li[u]; li[u] = li[u-1]; li[u-1] = ti; }                 \
    }

__global__ __launch_bounds__(256) void knn_select(
    const float* __restrict__ qm, const float* __restrict__ km)
{
    __shared__ float qs[64];
    __shared__ float ms[256 * 8];
    __shared__ int   mi[256 * 8];
    __shared__ int   s_list[CAP];
    __shared__ int   s_cnt;
    __shared__ float s_cut;
    const int q = blockIdx.x, tid = threadIdx.x;

    if (tid < 64) qs[tid] = qm[(size_t)q * DD + tid];
    if (tid == 0) s_cnt = 0;

    // ---- phase A: per-thread top-8 of half-mins (values cached) ----
    float hv[4];
    float l[8];
    #pragma unroll
    for (int i = 0; i < 8; i++) l[i] = CUDART_INF_F;
    #pragma unroll
    for (int r = 0; r < 4; r++) {
        const int h = tid + r * 256;
        hv[r] = (h < NHALF) ? g_hmin[(size_t)q * NHP + h] : CUDART_INF_F;
        float s = hv[r];
        if (s < l[7]) {
            l[7] = s;
            #pragma unroll
            for (int u = 7; u > 0; u--)
                if (l[u] < l[u-1]) { float ts = l[u]; l[u] = l[u-1]; l[u-1] = ts; }
        }
    }
    #pragma unroll
    for (int m = 0; m < 8; m++) ms[tid * 8 + m] = l[m];

    for (int st = 128; st >= 1; st >>= 1) {
        __syncthreads();
        if (tid < st) {
            const int o = (tid + st) * 8;
            #pragma unroll 1
            for (int m = 0; m < 8; m++) {
                float s = ms[o + m];
                if (s >= l[7]) break;
                l[7] = s;
                #pragma unroll
                for (int u = 7; u > 0; u--)
                    if (l[u] < l[u-1]) { float ts = l[u]; l[u] = l[u-1]; l[u-1] = ts; }
            }
            #pragma unroll
            for (int m = 0; m < 8; m++) ms[tid * 8 + m] = l[m];
        }
    }
    if (tid == 0) s_cut = l[7] + MARGIN;
    __syncthreads();

    // ---- phase B: compact candidate halves ----
    const float cut = s_cut;
    #pragma unroll
    for (int r = 0; r < 4; r++) {
        if (hv[r] <= cut) {
            int p = atomicAdd(&s_cnt, 1);
            if (p < CAP) s_list[p] = tid + r * 256;
        }
    }
    __syncthreads();
    const int cnt = (s_cnt < CAP) ? s_cnt : CAP;

    // ---- phase C: exact fp32 rescore of cnt*64 keys ----
    int li[8];
    #pragma unroll
    for (int i = 0; i < 8; i++) { l[i] = CUDART_INF_F; li[i] = 0x7FFFFFFF; }

    const float4* qp = (const float4*)qs;
    for (int u = tid; u < cnt * 64; u += 256) {
        const int j = s_list[u >> 6] * 64 + (u & 63);
        if (j < NK) {
            const float4* kp = (const float4*)(km + (size_t)j * DD);
            float dot = 0.f, ks = 0.f;
            #pragma unroll
            for (int w = 0; w < 16; w++) {
                float4 kv = kp[w];
                float4 qv = qp[w];
                dot = fmaf(kv.x, qv.x, dot); ks = fmaf(kv.x, kv.x, ks);
                dot = fmaf(kv.y, qv.y, dot); ks = fmaf(kv.y, kv.y, ks);
                dot = fmaf(kv.z, qv.z, dot); ks = fmaf(kv.z, kv.z, ks);
                dot = fmaf(kv.w, qv.w, dot); ks = fmaf(kv.w, kv.w, ks);
            }
            float s = fmaf(-2.f, dot, ks);
            INS8T(s, j);
        }
    }
    #pragma unroll
    for (int m = 0; m < 8; m++) { ms[tid * 8 + m] = l[m]; mi[tid * 8 + m] = li[m]; }

    for (int st = 128; st >= 1; st >>= 1) {
        __syncthreads();
        if (tid < st) {
            const int o = (tid + st) * 8;
            #pragma unroll 1
            for (int m = 0; m < 8; m++) {
                float s = ms[o + m];
                int   j = mi[o + m];
                bool better = (s < l[7]) || (s == l[7] && j < li[7]);
                if (!better) break;
                l[7] = s; li[7] = j;
                #pragma unroll
                for (int u = 7; u > 0; u--)
                    if (l[u] < l[u-1] || (l[u] == l[u-1] && li[u] < li[u-1])) {
                        float ts = l[u]; l[u] = l[u-1]; l[u-1] = ts;
                        int ti = li[u]; li[u] = li[u-1]; li[u-1] = ti;
                    }
            }
            #pragma unroll
            for (int m = 0; m < 8; m++) { ms[tid * 8 + m] = l[m]; mi[tid * 8 + m] = li[m]; }
        }
    }
    if (tid == 0) {
        #pragma unroll
        for (int m = 0; m < 8; m++) g_topidx[q * 8 + m] = li[m];
    }
}

// ======================================================================
// Kernel 3: gather obs[idx] -> out [8, 256, 3072]
// ======================================================================
__global__ __launch_bounds__(256) void knn_gather_kernel(
    const float* __restrict__ obs, float* __restrict__ out)
{
    const int b  = blockIdx.x;
    const int kk = b >> 8;
    const int q  = b & 255;
    const int src = g_topidx[q * 8 + kk];

    const float4* s = (const float4*)(obs + (size_t)src * OBS_ELEMS);
    float4*       d = (float4*)(out + ((size_t)kk * NQ + q) * OBS_ELEMS);

    #pragma unroll
    for (int i = threadIdx.x; i < OBS_ELEMS / 4; i += 256)
        d[i] = s[i];
}

// ======================================================================
extern "C" void kernel_launch(void* const* d_in, const int* in_sizes, int n_in,
                              void* d_out, int out_size)
{
    const float* q   = (const float*)d_in[0];
    const float* k   = (const float*)d_in[1];
    const float* obs = (const float*)d_in[2];
    float* out = (float*)d_out;

    cudaFuncSetAttribute(knn_score_min,
                         cudaFuncAttributeMaxDynamicSharedMemorySize, SM_TOTAL);

    knn_score_min<<<dim3(NKT, 2), 256, SM_TOTAL>>>(q, k);
    knn_select<<<NQ, 256>>>(q, k);
    knn_gather_kernel<<<NQ * 8, 256>>>(obs, out);
}

// round 8
// speedup vs baseline: 1.3609x; 1.3175x over previous
#include <cuda_runtime.h>
#include <cuda_bf16.h>
#include <math_constants.h>
#include <cstdint>

#define NQ        256
#define NK        50000
#define DD        64
#define KT        128
#define NKT       391          // ceil(50000/128)
#define GRP       16           // candidate granularity (keys per group)
#define NHG       (NKT * 8)    // 3128 groups
#define NHGP      3136         // padded
#define OBS_ELEMS 3072
#define CAP       128
#define MARGIN    1.0f         // >> 2x single-bf16 score error bound

// ---- static device scratch ----
__device__ float g_hmin[NQ * NHGP];   // per-(query, 16-key-group) min approx score
__device__ int   g_topidx[NQ * 8];

// ---- kernel-1 smem (bytes): 2 tiles 128x72 bf16 + ksq ----
#define TSTRIDE_B  144
#define SM_Q   0
#define SM_K   18432
#define SM_KSQ 36864
#define SM_TOTAL 37376

// ============================ helpers ============================
__device__ __forceinline__ uint32_t smem_u32(const void* p) {
    uint32_t a;
    asm("{ .reg .u64 t; cvta.to.shared.u64 t, %1; cvt.u32.u64 %0, t; }" : "=r"(a) : "l"(p));
    return a;
}
__device__ __forceinline__ void ldsm_x4(uint32_t& r0, uint32_t& r1, uint32_t& r2,
                                        uint32_t& r3, uint32_t a) {
    asm volatile("ldmatrix.sync.aligned.m8n8.x4.shared.b16 {%0,%1,%2,%3}, [%4];"
                 : "=r"(r0), "=r"(r1), "=r"(r2), "=r"(r3) : "r"(a));
}
__device__ __forceinline__ void mma_bf16(float& c0, float& c1, float& c2, float& c3,
                                         uint32_t a0, uint32_t a1, uint32_t a2, uint32_t a3,
                                         uint32_t b0, uint32_t b1) {
    asm volatile("mma.sync.aligned.m16n8k16.row.col.f32.bf16.bf16.f32 "
                 "{%0,%1,%2,%3},{%4,%5,%6,%7},{%8,%9},{%0,%1,%2,%3};"
                 : "+f"(c0), "+f"(c1), "+f"(c2), "+f"(c3)
                 : "r"(a0), "r"(a1), "r"(a2), "r"(a3), "r"(b0), "r"(b1));
}

// convert 32 floats -> bf16 row chunk, accumulate sum of squares
__device__ __forceinline__ void cvt_row_bf16(char* dst, const float4* __restrict__ s,
                                             float& ss) {
    uint2* d = (uint2*)dst;
    #pragma unroll
    for (int i = 0; i < 8; i++) {
        float4 v = s[i];
        ss = fmaf(v.x, v.x, ss); ss = fmaf(v.y, v.y, ss);
        ss = fmaf(v.z, v.z, ss); ss = fmaf(v.w, v.w, ss);
        __nv_bfloat162 p0 = __floats2bfloat162_rn(v.x, v.y);
        __nv_bfloat162 p1 = __floats2bfloat162_rn(v.z, v.w);
        uint2 u;
        u.x = *(uint32_t*)&p0;
        u.y = *(uint32_t*)&p1;
        d[i] = u;
    }
}

// ======================================================================
// Kernel 1: bf16 mma.sync score GEMM -> per-(query, 16-key-group) MIN
// grid (391, 2), 256 threads (8 warps: 4 m-rows x 2 n-cols)
// ======================================================================
__global__ __launch_bounds__(256, 3) void knn_score_min(
    const float* __restrict__ qm, const float* __restrict__ km)
{
    extern __shared__ char smem[];
    const uint32_t sb = smem_u32(smem);
    const int tid  = threadIdx.x;
    const int wid  = tid >> 5;
    const int lane = tid & 31;
    const int k0   = blockIdx.x * KT;
    const int q0   = blockIdx.y * 128;

    float* ksq = (float*)(smem + SM_KSQ);

    // ---- load + convert q/k tiles, compute ksq ----
    {
        const int row = tid >> 1, hf = tid & 1;
        float dummy = 0.f;
        cvt_row_bf16(smem + SM_Q + row * TSTRIDE_B + hf * 64,
                     (const float4*)(qm + (size_t)(q0 + row) * DD + hf * 32), dummy);
        const int j = k0 + row;
        char* krow = smem + SM_K + row * TSTRIDE_B + hf * 64;
        float ss = 0.f;
        if (j < NK) {
            cvt_row_bf16(krow, (const float4*)(km + (size_t)j * DD + hf * 32), ss);
        } else {
            uint2 z = make_uint2(0u, 0u);
            uint2* d = (uint2*)krow;
            #pragma unroll
            for (int i = 0; i < 8; i++) d[i] = z;
        }
        float tot = ss + __shfl_xor_sync(0xFFFFFFFFu, ss, 1);
        if (hf == 0) ksq[row] = (j < NK) ? tot : CUDART_INF_F;
    }
    __syncthreads();

    // ---- warp GEMM: 32(m) x 64(n), single pass ----
    const int mrow = wid >> 1;
    const int ncol = wid & 1;

    float acc[2][8][4];
    #pragma unroll
    for (int mt = 0; mt < 2; mt++)
        #pragma unroll
        for (int nt = 0; nt < 8; nt++)
            #pragma unroll
            for (int c = 0; c < 4; c++) acc[mt][nt][c] = 0.f;

    #pragma unroll
    for (int ks16 = 0; ks16 < 4; ks16++) {
        const uint32_t dby = ks16 * 32;
        uint32_t a[2][4];
        #pragma unroll
        for (int mt = 0; mt < 2; mt++) {
            uint32_t addr = sb + SM_Q
                + (uint32_t)(mrow * 32 + mt * 16 + (lane & 15)) * TSTRIDE_B
                + dby + ((lane >> 4) << 4);
            ldsm_x4(a[mt][0], a[mt][1], a[mt][2], a[mt][3], addr);
        }
        uint32_t b[8][2];
        #pragma unroll
        for (int np = 0; np < 4; np++) {
            uint32_t n = (uint32_t)(ncol * 64 + np * 16 + ((lane >> 4) << 3) + (lane & 7));
            uint32_t addr = sb + SM_K + n * TSTRIDE_B + dby + (((lane >> 3) & 1) << 4);
            ldsm_x4(b[np * 2][0], b[np * 2][1], b[np * 2 + 1][0], b[np * 2 + 1][1], addr);
        }
        #pragma unroll
        for (int mt = 0; mt < 2; mt++)
            #pragma unroll
            for (int nt = 0; nt < 8; nt++)
                mma_bf16(acc[mt][nt][0], acc[mt][nt][1], acc[mt][nt][2], acc[mt][nt][3],
                         a[mt][0], a[mt][1], a[mt][2], a[mt][3],
                         b[nt][0], b[nt][1]);
    }

    // ---- epilogue: per-(row, 16-col-group) min of (ksq - 2*dot) ----
    {
        const int g = lane >> 2, t = lane & 3;
        #pragma unroll
        for (int mt = 0; mt < 2; mt++) {
            const int rowb = q0 + mrow * 32 + mt * 16 + g;
            #pragma unroll
            for (int gi = 0; gi < 4; gi++) {
                float m0 = CUDART_INF_F, m1 = CUDART_INF_F;
                #pragma unroll
                for (int e = 0; e < 2; e++) {
                    const int nt = gi * 2 + e;
                    const int col = ncol * 64 + nt * 8 + t * 2;
                    const float kq0 = ksq[col], kq1 = ksq[col + 1];
                    m0 = fminf(m0, fminf(fmaf(-2.f, acc[mt][nt][0], kq0),
                                         fmaf(-2.f, acc[mt][nt][1], kq1)));
                    m1 = fminf(m1, fminf(fmaf(-2.f, acc[mt][nt][2], kq0),
                                         fmaf(-2.f, acc[mt][nt][3], kq1)));
                }
                m0 = fminf(m0, __shfl_xor_sync(0xFFFFFFFFu, m0, 1));
                m0 = fminf(m0, __shfl_xor_sync(0xFFFFFFFFu, m0, 2));
                m1 = fminf(m1, __shfl_xor_sync(0xFFFFFFFFu, m1, 1));
                m1 = fminf(m1, __shfl_xor_sync(0xFFFFFFFFu, m1, 2));
                if (t == 0) {
                    const int grp = blockIdx.x * 8 + ncol * 4 + gi;
                    g_hmin[(size_t)rowb * NHGP + grp]       = m0;
                    g_hmin[(size_t)(rowb + 8) * NHGP + grp] = m1;
                }
            }
        }
    }
}

// ======================================================================
// Kernel 2 (fused): cutoff from group-mins -> compact -> exact fp32
//                   rescore -> exact top-8. grid NQ, 256 threads.
// ======================================================================
#define INS8T(s_, j_)                                                            \
    if ((s_) < l[7] || ((s_) == l[7] && (j_) < li[7])) {                         \
        l[7] = (s_); li[7] = (j_);                                               \
        _Pragma("unroll")                                                        \
        for (int u = 7; u > 0; u--)                                              \
            if (l[u] < l[u-1] || (l[u] == l[u-1] && li[u] < li[u-1])) {          \
                float ts = l[u]; l[u] = l[u-1]; l[u-1] = ts;                     \
                int ti = li[u]; li[u] = li[u-1]; li[u-1] = ti; }                 \
    }

__global__ __launch_bounds__(256) void knn_select(
    const float* __restrict__ qm, const float* __restrict__ km)
{
    __shared__ float qs[64];
    __shared__ float ms[256 * 8];
    __shared__ int   mi[256 * 8];
    __shared__ int   s_list[CAP];
    __shared__ int   s_cnt;
    __shared__ float s_cut;
    const int q = blockIdx.x, tid = threadIdx.x;

    if (tid < 64) qs[tid] = qm[(size_t)q * DD + tid];
    if (tid == 0) s_cnt = 0;

    const float* hrow = &g_hmin[(size_t)q * NHGP];

    // ---- phase A: per-thread top-8 of group-mins ----
    float l[8];
    #pragma unroll
    for (int i = 0; i < 8; i++) l[i] = CUDART_INF_F;
    #pragma unroll
    for (int r = 0; r < 13; r++) {
        const int h = tid + r * 256;
        if (h < NHG) {
            float s = hrow[h];
            if (s < l[7]) {
                l[7] = s;
                #pragma unroll
                for (int u = 7; u > 0; u--)
                    if (l[u] < l[u-1]) { float ts = l[u]; l[u] = l[u-1]; l[u-1] = ts; }
            }
        }
    }
    #pragma unroll
    for (int m = 0; m < 8; m++) ms[tid * 8 + m] = l[m];

    for (int st = 128; st >= 1; st >>= 1) {
        __syncthreads();
        if (tid < st) {
            const int o = (tid + st) * 8;
            #pragma unroll 1
            for (int m = 0; m < 8; m++) {
                float s = ms[o + m];
                if (s >= l[7]) break;
                l[7] = s;
                #pragma unroll
                for (int u = 7; u > 0; u--)
                    if (l[u] < l[u-1]) { float ts = l[u]; l[u] = l[u-1]; l[u-1] = ts; }
            }
            #pragma unroll
            for (int m = 0; m < 8; m++) ms[tid * 8 + m] = l[m];
        }
    }
    if (tid == 0) s_cut = l[7] + MARGIN;
    __syncthreads();

    // ---- phase B: compact candidate 16-key groups ----
    const float cut = s_cut;
    #pragma unroll
    for (int r = 0; r < 13; r++) {
        const int h = tid + r * 256;
        if (h < NHG && hrow[h] <= cut) {
            int p = atomicAdd(&s_cnt, 1);
            if (p < CAP) s_list[p] = h;
        }
    }
    __syncthreads();
    const int cnt = (s_cnt < CAP) ? s_cnt : CAP;

    // ---- phase C: exact fp32 rescore of cnt*16 keys ----
    int li[8];
    #pragma unroll
    for (int i = 0; i < 8; i++) { l[i] = CUDART_INF_F; li[i] = 0x7FFFFFFF; }

    const float4* qp = (const float4*)qs;
    for (int u = tid; u < cnt * GRP; u += 256) {
        const int j = s_list[u >> 4] * GRP + (u & 15);
        if (j < NK) {
            const float4* kp = (const float4*)(km + (size_t)j * DD);
            float dot = 0.f, ks = 0.f;
            #pragma unroll
            for (int w = 0; w < 16; w++) {
                float4 kv = kp[w];
                float4 qv = qp[w];
                dot = fmaf(kv.x, qv.x, dot); ks = fmaf(kv.x, kv.x, ks);
                dot = fmaf(kv.y, qv.y, dot); ks = fmaf(kv.y, kv.y, ks);
                dot = fmaf(kv.z, qv.z, dot); ks = fmaf(kv.z, kv.z, ks);
                dot = fmaf(kv.w, qv.w, dot); ks = fmaf(kv.w, kv.w, ks);
            }
            float s = fmaf(-2.f, dot, ks);
            INS8T(s, j);
        }
    }
    #pragma unroll
    for (int m = 0; m < 8; m++) { ms[tid * 8 + m] = l[m]; mi[tid * 8 + m] = li[m]; }

    for (int st = 128; st >= 1; st >>= 1) {
        __syncthreads();
        if (tid < st) {
            const int o = (tid + st) * 8;
            #pragma unroll 1
            for (int m = 0; m < 8; m++) {
                float s = ms[o + m];
                int   j = mi[o + m];
                bool better = (s < l[7]) || (s == l[7] && j < li[7]);
                if (!better) break;
                l[7] = s; li[7] = j;
                #pragma unroll
                for (int u = 7; u > 0; u--)
                    if (l[u] < l[u-1] || (l[u] == l[u-1] && li[u] < li[u-1])) {
                        float ts = l[u]; l[u] = l[u-1]; l[u-1] = ts;
                        int ti = li[u]; li[u] = li[u-1]; li[u-1] = ti;
                    }
            }
            #pragma unroll
            for (int m = 0; m < 8; m++) { ms[tid * 8 + m] = l[m]; mi[tid * 8 + m] = li[m]; }
        }
    }
    if (tid == 0) {
        #pragma unroll
        for (int m = 0; m < 8; m++) g_topidx[q * 8 + m] = li[m];
    }
}

// ======================================================================
// Kernel 3: gather obs[idx] -> out [8, 256, 3072]
// ======================================================================
__global__ __launch_bounds__(256) void knn_gather_kernel(
    const float* __restrict__ obs, float* __restrict__ out)
{
    const int b  = blockIdx.x;
    const int kk = b >> 8;
    const int q  = b & 255;
    const int src = g_topidx[q * 8 + kk];

    const float4* s = (const float4*)(obs + (size_t)src * OBS_ELEMS);
    float4*       d = (float4*)(out + ((size_t)kk * NQ + q) * OBS_ELEMS);

    #pragma unroll
    for (int i = threadIdx.x; i < OBS_ELEMS / 4; i += 256)
        d[i] = s[i];
}

// ======================================================================
extern "C" void kernel_launch(void* const* d_in, const int* in_sizes, int n_in,
                              void* d_out, int out_size)
{
    const float* q   = (const float*)d_in[0];
    const float* k   = (const float*)d_in[1];
    const float* obs = (const float*)d_in[2];
    float* out = (float*)d_out;

    cudaFuncSetAttribute(knn_score_min,
                         cudaFuncAttributeMaxDynamicSharedMemorySize, SM_TOTAL);

    knn_score_min<<<dim3(NKT, 2), 256, SM_TOTAL>>>(q, k);
    knn_select<<<NQ, 256>>>(q, k);
    knn_gather_kernel<<<NQ * 8, 256>>>(obs, out);
}

// round 9
// speedup vs baseline: 1.4692x; 1.0795x over previous
#include <cuda_runtime.h>
#include <cuda_bf16.h>
#include <math_constants.h>
#include <cstdint>

#define NQ        256
#define NK        50000
#define DD        64
#define KT        128
#define NKT       391          // ceil(50000/128)
#define GRP       16           // candidate granularity (keys per group)
#define NHG       (NKT * 8)    // 3128 groups
#define NHGP      3136         // padded
#define OBS_ELEMS 3072
#define CAP       128
#define MARGIN    1.0f         // >> 2x single-bf16 score error bound

// ---- static device scratch ----
__device__ __align__(16) float g_hmin[NQ * NHGP];
__device__ int   g_topidx[NQ * 8];

// ---- kernel-1 smem (bytes) ----
#define TSTRIDE_B  144
#define SM_Q     0             // 256 x 144 = 36864
#define SM_K     36864         // 128 x 144 = 18432
#define SM_KSQ   55296         // 128 f32 = 512
#define SM_STAGE 55808         // 256 x 8 f32 = 8192
#define SM_TOTAL 64000

// ============================ helpers ============================
__device__ __forceinline__ uint32_t smem_u32(const void* p) {
    uint32_t a;
    asm("{ .reg .u64 t; cvta.to.shared.u64 t, %1; cvt.u32.u64 %0, t; }" : "=r"(a) : "l"(p));
    return a;
}
__device__ __forceinline__ void ldsm_x4(uint32_t& r0, uint32_t& r1, uint32_t& r2,
                                        uint32_t& r3, uint32_t a) {
    asm volatile("ldmatrix.sync.aligned.m8n8.x4.shared.b16 {%0,%1,%2,%3}, [%4];"
                 : "=r"(r0), "=r"(r1), "=r"(r2), "=r"(r3) : "r"(a));
}
__device__ __forceinline__ void mma_bf16(float& c0, float& c1, float& c2, float& c3,
                                         uint32_t a0, uint32_t a1, uint32_t a2, uint32_t a3,
                                         uint32_t b0, uint32_t b1) {
    asm volatile("mma.sync.aligned.m16n8k16.row.col.f32.bf16.bf16.f32 "
                 "{%0,%1,%2,%3},{%4,%5,%6,%7},{%8,%9},{%0,%1,%2,%3};"
                 : "+f"(c0), "+f"(c1), "+f"(c2), "+f"(c3)
                 : "r"(a0), "r"(a1), "r"(a2), "r"(a3), "r"(b0), "r"(b1));
}

// convert 32 floats -> bf16 row chunk, accumulate sum of squares
__device__ __forceinline__ void cvt_row_bf16(char* dst, const float4* __restrict__ s,
                                             float& ss) {
    uint2* d = (uint2*)dst;
    #pragma unroll
    for (int i = 0; i < 8; i++) {
        float4 v = s[i];
        ss = fmaf(v.x, v.x, ss); ss = fmaf(v.y, v.y, ss);
        ss = fmaf(v.z, v.z, ss); ss = fmaf(v.w, v.w, ss);
        __nv_bfloat162 p0 = __floats2bfloat162_rn(v.x, v.y);
        __nv_bfloat162 p1 = __floats2bfloat162_rn(v.z, v.w);
        uint2 u;
        u.x = *(uint32_t*)&p0;
        u.y = *(uint32_t*)&p1;
        d[i] = u;
    }
}

// ======================================================================
// Kernel 1: bf16 mma.sync score GEMM -> per-(query, 16-key-group) MIN
// grid 391, 512 threads (16 warps: 8 m-rows x 2 n-cols), 256q x 128k per CTA
// ======================================================================
__global__ __launch_bounds__(512, 1) void knn_score_min(
    const float* __restrict__ qm, const float* __restrict__ km)
{
    extern __shared__ char smem[];
    const uint32_t sb = smem_u32(smem);
    const int tid  = threadIdx.x;
    const int wid  = tid >> 5;
    const int lane = tid & 31;
    const int k0   = blockIdx.x * KT;

    float* ksq   = (float*)(smem + SM_KSQ);
    float* stage = (float*)(smem + SM_STAGE);

    // ---- load + convert tiles ----
    {
        const int row = tid >> 1, hf = tid & 1;
        // q: 512 threads cover 256 rows x 2 halves
        float dummy = 0.f;
        cvt_row_bf16(smem + SM_Q + row * TSTRIDE_B + hf * 64,
                     (const float4*)(qm + (size_t)row * DD + hf * 32), dummy);
        // k: first 8 warps cover 128 rows x 2 halves
        if (tid < 256) {
            const int j = k0 + row;
            char* krow = smem + SM_K + row * TSTRIDE_B + hf * 64;
            float ss = 0.f;
            if (j < NK) {
                cvt_row_bf16(krow, (const float4*)(km + (size_t)j * DD + hf * 32), ss);
            } else {
                uint2 z = make_uint2(0u, 0u);
                uint2* d = (uint2*)krow;
                #pragma unroll
                for (int i = 0; i < 8; i++) d[i] = z;
            }
            float tot = ss + __shfl_xor_sync(0xFFFFFFFFu, ss, 1);
            if (hf == 0) ksq[row] = (j < NK) ? tot : CUDART_INF_F;
        }
    }
    __syncthreads();

    // ---- warp GEMM: 32(m) x 64(n) per warp ----
    const int mrow = wid >> 1;          // 0..7
    const int ncol = wid & 1;           // 0..1

    float acc[2][8][4];
    #pragma unroll
    for (int mt = 0; mt < 2; mt++)
        #pragma unroll
        for (int nt = 0; nt < 8; nt++)
            #pragma unroll
            for (int c = 0; c < 4; c++) acc[mt][nt][c] = 0.f;

    #pragma unroll
    for (int ks16 = 0; ks16 < 4; ks16++) {
        const uint32_t dby = ks16 * 32;
        uint32_t a[2][4];
        #pragma unroll
        for (int mt = 0; mt < 2; mt++) {
            uint32_t addr = sb + SM_Q
                + (uint32_t)(mrow * 32 + mt * 16 + (lane & 15)) * TSTRIDE_B
                + dby + ((lane >> 4) << 4);
            ldsm_x4(a[mt][0], a[mt][1], a[mt][2], a[mt][3], addr);
        }
        uint32_t b[8][2];
        #pragma unroll
        for (int np = 0; np < 4; np++) {
            uint32_t n = (uint32_t)(ncol * 64 + np * 16 + ((lane >> 4) << 3) + (lane & 7));
            uint32_t addr = sb + SM_K + n * TSTRIDE_B + dby + (((lane >> 3) & 1) << 4);
            ldsm_x4(b[np * 2][0], b[np * 2][1], b[np * 2 + 1][0], b[np * 2 + 1][1], addr);
        }
        #pragma unroll
        for (int mt = 0; mt < 2; mt++)
            #pragma unroll
            for (int nt = 0; nt < 8; nt++)
                mma_bf16(acc[mt][nt][0], acc[mt][nt][1], acc[mt][nt][2], acc[mt][nt][3],
                         a[mt][0], a[mt][1], a[mt][2], a[mt][3],
                         b[nt][0], b[nt][1]);
    }

    // ---- epilogue: per-(row, 16-col-group) min -> smem stage ----
    {
        const int g = lane >> 2, t = lane & 3;
        #pragma unroll
        for (int mt = 0; mt < 2; mt++) {
            const int rowb = mrow * 32 + mt * 16 + g;
            #pragma unroll
            for (int gi = 0; gi < 4; gi++) {
                float m0 = CUDART_INF_F, m1 = CUDART_INF_F;
                #pragma unroll
                for (int e = 0; e < 2; e++) {
                    const int nt = gi * 2 + e;
                    const int col = ncol * 64 + nt * 8 + t * 2;
                    const float kq0 = ksq[col], kq1 = ksq[col + 1];
                    m0 = fminf(m0, fminf(fmaf(-2.f, acc[mt][nt][0], kq0),
                                         fmaf(-2.f, acc[mt][nt][1], kq1)));
                    m1 = fminf(m1, fminf(fmaf(-2.f, acc[mt][nt][2], kq0),
                                         fmaf(-2.f, acc[mt][nt][3], kq1)));
                }
                m0 = fminf(m0, __shfl_xor_sync(0xFFFFFFFFu, m0, 1));
                m0 = fminf(m0, __shfl_xor_sync(0xFFFFFFFFu, m0, 2));
                m1 = fminf(m1, __shfl_xor_sync(0xFFFFFFFFu, m1, 1));
                m1 = fminf(m1, __shfl_xor_sync(0xFFFFFFFFu, m1, 2));
                if (t == 0) {
                    const int gg = ncol * 4 + gi;
                    stage[rowb * 8 + gg]       = m0;
                    stage[(rowb + 8) * 8 + gg] = m1;
                }
            }
        }
    }
    __syncthreads();

    // ---- coalesced write-out: 512 threads x one float4 each ----
    {
        const int row = tid >> 1, half = tid & 1;
        float4 v = *(float4*)&stage[row * 8 + half * 4];
        *(float4*)&g_hmin[(size_t)row * NHGP + blockIdx.x * 8 + half * 4] = v;
    }
}

// ======================================================================
// Kernel 2 (fused): cutoff from group-mins -> compact -> exact fp32
//                   rescore -> exact top-8. grid NQ, 256 threads.
// ======================================================================
#define INS8T(s_, j_)                                                            \
    if ((s_) < l[7] || ((s_) == l[7] && (j_) < li[7])) {                         \
        l[7] = (s_); li[7] = (j_);                                               \
        _Pragma("unroll")                                                        \
        for (int u = 7; u > 0; u--)                                              \
            if (l[u] < l[u-1] || (l[u] == l[u-1] && li[u] < li[u-1])) {          \
                float ts = l[u]; l[u] = l[u-1]; l[u-1] = ts;                     \
                int ti = li[u]; li[u] = li[u-1]; li[u-1] = ti; }                 \
    }

__global__ __launch_bounds__(256) void knn_select(
    const float* __restrict__ qm, const float* __restrict__ km)
{
    __shared__ float qs[64];
    __shared__ float ms[256 * 8];
    __shared__ int   mi[256 * 8];
    __shared__ int   s_list[CAP];
    __shared__ int   s_cnt;
    __shared__ float s_cut;
    const int q = blockIdx.x, tid = threadIdx.x;

    if (tid < 64) qs[tid] = qm[(size_t)q * DD + tid];
    if (tid == 0) s_cnt = 0;

    const float* hrow = &g_hmin[(size_t)q * NHGP];

    // ---- phase A: per-thread top-8 of group-mins ----
    float l[8];
    #pragma unroll
    for (int i = 0; i < 8; i++) l[i] = CUDART_INF_F;
    #pragma unroll
    for (int r = 0; r < 13; r++) {
        const int h = tid + r * 256;
        if (h < NHG) {
            float s = hrow[h];
            if (s < l[7]) {
                l[7] = s;
                #pragma unroll
                for (int u = 7; u > 0; u--)
                    if (l[u] < l[u-1]) { float ts = l[u]; l[u] = l[u-1]; l[u-1] = ts; }
            }
        }
    }
    #pragma unroll
    for (int m = 0; m < 8; m++) ms[tid * 8 + m] = l[m];

    for (int st = 128; st >= 1; st >>= 1) {
        __syncthreads();
        if (tid < st) {
            const int o = (tid + st) * 8;
            #pragma unroll 1
            for (int m = 0; m < 8; m++) {
                float s = ms[o + m];
                if (s >= l[7]) break;
                l[7] = s;
                #pragma unroll
                for (int u = 7; u > 0; u--)
                    if (l[u] < l[u-1]) { float ts = l[u]; l[u] = l[u-1]; l[u-1] = ts; }
            }
            #pragma unroll
            for (int m = 0; m < 8; m++) ms[tid * 8 + m] = l[m];
        }
    }
    if (tid == 0) s_cut = l[7] + MARGIN;
    __syncthreads();

    // ---- phase B: compact candidate 16-key groups ----
    const float cut = s_cut;
    #pragma unroll
    for (int r = 0; r < 13; r++) {
        const int h = tid + r * 256;
        if (h < NHG && hrow[h] <= cut) {
            int p = atomicAdd(&s_cnt, 1);
            if (p < CAP) s_list[p] = h;
        }
    }
    __syncthreads();
    const int cnt = (s_cnt < CAP) ? s_cnt : CAP;

    // ---- phase C: exact fp32 rescore of cnt*16 keys ----
    int li[8];
    #pragma unroll
    for (int i = 0; i < 8; i++) { l[i] = CUDART_INF_F; li[i] = 0x7FFFFFFF; }

    const float4* qp = (const float4*)qs;
    for (int u = tid; u < cnt * GRP; u += 256) {
        const int j = s_list[u >> 4] * GRP + (u & 15);
        if (j < NK) {
            const float4* kp = (const float4*)(km + (size_t)j * DD);
            float dot = 0.f, ks = 0.f;
            #pragma unroll
            for (int w = 0; w < 16; w++) {
                float4 kv = kp[w];
                float4 qv = qp[w];
                dot = fmaf(kv.x, qv.x, dot); ks = fmaf(kv.x, kv.x, ks);
                dot = fmaf(kv.y, qv.y, dot); ks = fmaf(kv.y, kv.y, ks);
                dot = fmaf(kv.z, qv.z, dot); ks = fmaf(kv.z, kv.z, ks);
                dot = fmaf(kv.w, qv.w, dot); ks = fmaf(kv.w, kv.w, ks);
            }
            float s = fmaf(-2.f, dot, ks);
            INS8T(s, j);
        }
    }
    #pragma unroll
    for (int m = 0; m < 8; m++) { ms[tid * 8 + m] = l[m]; mi[tid * 8 + m] = li[m]; }

    for (int st = 128; st >= 1; st >>= 1) {
        __syncthreads();
        if (tid < st) {
            const int o = (tid + st) * 8;
            #pragma unroll 1
            for (int m = 0; m < 8; m++) {
                float s = ms[o + m];
                int   j = mi[o + m];
                bool better = (s < l[7]) || (s == l[7] && j < li[7]);
                if (!better) break;
                l[7] = s; li[7] = j;
                #pragma unroll
                for (int u = 7; u > 0; u--)
                    if (l[u] < l[u-1] || (l[u] == l[u-1] && li[u] < li[u-1])) {
                        float ts = l[u]; l[u] = l[u-1]; l[u-1] = ts;
                        int ti = li[u]; li[u] = li[u-1]; li[u-1] = ti;
                    }
            }
            #pragma unroll
            for (int m = 0; m < 8; m++) { ms[tid * 8 + m] = l[m]; mi[tid * 8 + m] = li[m]; }
        }
    }
    if (tid == 0) {
        #pragma unroll
        for (int m = 0; m < 8; m++) g_topidx[q * 8 + m] = li[m];
    }
}

// ======================================================================
// Kernel 3: gather obs[idx] -> out [8, 256, 3072]
// ======================================================================
__global__ __launch_bounds__(256) void knn_gather_kernel(
    const float* __restrict__ obs, float* __restrict__ out)
{
    const int b  = blockIdx.x;
    const int kk = b >> 8;
    const int q  = b & 255;
    const int src = g_topidx[q * 8 + kk];

    const float4* s = (const float4*)(obs + (size_t)src * OBS_ELEMS);
    float4*       d = (float4*)(out + ((size_t)kk * NQ + q) * OBS_ELEMS);

    #pragma unroll
    for (int i = threadIdx.x; i < OBS_ELEMS / 4; i += 256)
        d[i] = s[i];
}

// ======================================================================
extern "C" void kernel_launch(void* const* d_in, const int* in_sizes, int n_in,
                              void* d_out, int out_size)
{
    const float* q   = (const float*)d_in[0];
    const float* k   = (const float*)d_in[1];
    const float* obs = (const float*)d_in[2];
    float* out = (float*)d_out;

    cudaFuncSetAttribute(knn_score_min,
                         cudaFuncAttributeMaxDynamicSharedMemorySize, SM_TOTAL);

    knn_score_min<<<NKT, 512, SM_TOTAL>>>(q, k);
    knn_select<<<NQ, 256>>>(q, k);
    knn_gather_kernel<<<NQ * 8, 256>>>(obs, out);
}

// round 10
// speedup vs baseline: 1.6026x; 1.0908x over previous
#include <cuda_runtime.h>
#include <cuda_bf16.h>
#include <math_constants.h>
#include <cstdint>

#define NQ        256
#define NK        50000
#define DD        64
#define KT        128
#define NKT       391          // ceil(50000/128)
#define GRID1     148          // persistent CTAs for score kernel
#define GRP       16           // candidate granularity (keys per group)
#define NHG       (NKT * 8)    // 3128 groups (no padding; 3128 % 4 == 0)
#define OBS_ELEMS 3072
#define CAP       128
#define MARGIN    1.0f         // >> 2x single-bf16 score error bound

// ---- static device scratch ----
__device__ __align__(16) float g_hmin[NQ * NHG];
__device__ int   g_topidx[NQ * 8];

// ---- kernel-1 smem (bytes) ----
#define TSTRIDE_B  144
#define SM_Q     0             // 256 x 144 bf16 rows      = 36864
#define SM_K0    36864         // 128 x 144                = 18432
#define SM_K1    55296         //                          = 18432
#define SM_KSQ0  73728         // 128 f32                  = 512
#define SM_KSQ1  74240         //                          = 512
#define SM_ST32  74752         // fp32 k staging 128x256B  = 32768
#define SM_HST   107520        // hmin stage 256x8 f32     = 8192
#define SM_TOTAL 115712

// ============================ helpers ============================
__device__ __forceinline__ uint32_t smem_u32(const void* p) {
    uint32_t a;
    asm("{ .reg .u64 t; cvta.to.shared.u64 t, %1; cvt.u32.u64 %0, t; }" : "=r"(a) : "l"(p));
    return a;
}
__device__ __forceinline__ void ldsm_x4(uint32_t& r0, uint32_t& r1, uint32_t& r2,
                                        uint32_t& r3, uint32_t a) {
    asm volatile("ldmatrix.sync.aligned.m8n8.x4.shared.b16 {%0,%1,%2,%3}, [%4];"
                 : "=r"(r0), "=r"(r1), "=r"(r2), "=r"(r3) : "r"(a));
}
__device__ __forceinline__ void mma_bf16(float& c0, float& c1, float& c2, float& c3,
                                         uint32_t a0, uint32_t a1, uint32_t a2, uint32_t a3,
                                         uint32_t b0, uint32_t b1) {
    asm volatile("mma.sync.aligned.m16n8k16.row.col.f32.bf16.bf16.f32 "
                 "{%0,%1,%2,%3},{%4,%5,%6,%7},{%8,%9},{%0,%1,%2,%3};"
                 : "+f"(c0), "+f"(c1), "+f"(c2), "+f"(c3)
                 : "r"(a0), "r"(a1), "r"(a2), "r"(a3), "r"(b0), "r"(b1));
}
__device__ __forceinline__ void cp_async16(uint32_t dst, const void* src) {
    asm volatile("cp.async.cg.shared.global [%0], [%1], 16;" :: "r"(dst), "l"(src));
}

// convert 32 floats -> bf16 row chunk in smem, accumulate sum of squares
__device__ __forceinline__ void cvt_row_bf16(char* dst, const float4* __restrict__ s,
                                             float& ss) {
    uint2* d = (uint2*)dst;
    #pragma unroll
    for (int i = 0; i < 8; i++) {
        float4 v = s[i];
        ss = fmaf(v.x, v.x, ss); ss = fmaf(v.y, v.y, ss);
        ss = fmaf(v.z, v.z, ss); ss = fmaf(v.w, v.w, ss);
        __nv_bfloat162 p0 = __floats2bfloat162_rn(v.x, v.y);
        __nv_bfloat162 p1 = __floats2bfloat162_rn(v.z, v.w);
        uint2 u;
        u.x = *(uint32_t*)&p0;
        u.y = *(uint32_t*)&p1;
        d[i] = u;
    }
}

// ======================================================================
// Kernel 1: persistent pipelined bf16 GEMM -> per-(query,16-key-group) MIN
// grid 148, 512 threads (16 warps: 8 m-rows x 2 n-cols), 256q x 128k tiles
// ======================================================================
__global__ __launch_bounds__(512, 1) void knn_score_min(
    const float* __restrict__ qm, const float* __restrict__ km)
{
    extern __shared__ char smem[];
    const uint32_t sb = smem_u32(smem);
    const int tid  = threadIdx.x;
    const int wid  = tid >> 5;
    const int lane = tid & 31;
    const int c    = blockIdx.x;
    const int n_it = (c < NKT - 2 * GRID1) ? 3 : 2;   // 95 CTAs do 3, rest 2

    float* stage = (float*)(smem + SM_HST);

    // ---- prologue: load+convert q (all 512 thr) and k tile 'c' (thr<256) ----
    {
        const int row = tid >> 1, hf = tid & 1;
        float dummy = 0.f;
        cvt_row_bf16(smem + SM_Q + row * TSTRIDE_B + hf * 64,
                     (const float4*)(qm + (size_t)row * DD + hf * 32), dummy);
        if (tid < 256) {
            // prologue tiles (c <= 147) are always fully in-bounds
            const int j = c * KT + row;
            float ss = 0.f;
            cvt_row_bf16(smem + SM_K0 + row * TSTRIDE_B + hf * 64,
                         (const float4*)(km + (size_t)j * DD + hf * 32), ss);
            float tot = ss + __shfl_xor_sync(0xFFFFFFFFu, ss, 1);
            if (hf == 0) ((float*)(smem + SM_KSQ0))[row] = tot;
        }
    }
    __syncthreads();

    const int mrow = wid >> 1;          // 0..7
    const int ncol = wid & 1;           // 0..1
    int p = 0;

    for (int it = 0; it < n_it; it++) {
        const int t = c + it * GRID1;
        const bool have_next = (it + 1 < n_it);

        // ---- prefetch next fp32 k tile via cp.async (quarter-row/thread) ----
        if (have_next) {
            const int tn = t + GRID1;
            const int row = tid >> 2, qtr = tid & 3;
            int j = tn * KT + row;
            if (j >= NK) j = NK - 1;                     // clamp; ksq set INF later
            const char* src = (const char*)(km + (size_t)j * DD) + qtr * 64;
            uint32_t dst = sb + SM_ST32 + row * 256 + qtr * 64;
            #pragma unroll
            for (int i = 0; i < 4; i++)
                cp_async16(dst + i * 16, src + i * 16);
            asm volatile("cp.async.commit_group;" ::: "memory");
        }

        // ---- GEMM from buffer p ----
        const uint32_t kbase = sb + (p ? SM_K1 : SM_K0);
        const float* ksq = (const float*)(smem + (p ? SM_KSQ1 : SM_KSQ0));

        float acc[2][8][4];
        #pragma unroll
        for (int mt = 0; mt < 2; mt++)
            #pragma unroll
            for (int nt = 0; nt < 8; nt++)
                #pragma unroll
                for (int cc = 0; cc < 4; cc++) acc[mt][nt][cc] = 0.f;

        #pragma unroll
        for (int ks16 = 0; ks16 < 4; ks16++) {
            const uint32_t dby = ks16 * 32;
            uint32_t a[2][4];
            #pragma unroll
            for (int mt = 0; mt < 2; mt++) {
                uint32_t addr = sb + SM_Q
                    + (uint32_t)(mrow * 32 + mt * 16 + (lane & 15)) * TSTRIDE_B
                    + dby + ((lane >> 4) << 4);
                ldsm_x4(a[mt][0], a[mt][1], a[mt][2], a[mt][3], addr);
            }
            uint32_t b[8][2];
            #pragma unroll
            for (int np = 0; np < 4; np++) {
                uint32_t n = (uint32_t)(ncol * 64 + np * 16 + ((lane >> 4) << 3) + (lane & 7));
                uint32_t addr = kbase + n * TSTRIDE_B + dby + (((lane >> 3) & 1) << 4);
                ldsm_x4(b[np * 2][0], b[np * 2][1], b[np * 2 + 1][0], b[np * 2 + 1][1], addr);
            }
            #pragma unroll
            for (int mt = 0; mt < 2; mt++)
                #pragma unroll
                for (int nt = 0; nt < 8; nt++)
                    mma_bf16(acc[mt][nt][0], acc[mt][nt][1], acc[mt][nt][2], acc[mt][nt][3],
                             a[mt][0], a[mt][1], a[mt][2], a[mt][3],
                             b[nt][0], b[nt][1]);
        }

        // ---- epilogue: per-(row, 16-col-group) min -> smem stage ----
        {
            const int g = lane >> 2, tq = lane & 3;
            #pragma unroll
            for (int mt = 0; mt < 2; mt++) {
                const int rowb = mrow * 32 + mt * 16 + g;
                #pragma unroll
                for (int gi = 0; gi < 4; gi++) {
                    float m0 = CUDART_INF_F, m1 = CUDART_INF_F;
                    #pragma unroll
                    for (int e = 0; e < 2; e++) {
                        const int nt = gi * 2 + e;
                        const int col = ncol * 64 + nt * 8 + tq * 2;
                        const float kq0 = ksq[col], kq1 = ksq[col + 1];
                        m0 = fminf(m0, fminf(fmaf(-2.f, acc[mt][nt][0], kq0),
                                             fmaf(-2.f, acc[mt][nt][1], kq1)));
                        m1 = fminf(m1, fminf(fmaf(-2.f, acc[mt][nt][2], kq0),
                                             fmaf(-2.f, acc[mt][nt][3], kq1)));
                    }
                    m0 = fminf(m0, __shfl_xor_sync(0xFFFFFFFFu, m0, 1));
                    m0 = fminf(m0, __shfl_xor_sync(0xFFFFFFFFu, m0, 2));
                    m1 = fminf(m1, __shfl_xor_sync(0xFFFFFFFFu, m1, 1));
                    m1 = fminf(m1, __shfl_xor_sync(0xFFFFFFFFu, m1, 2));
                    if (tq == 0) {
                        const int gg = ncol * 4 + gi;
                        stage[rowb * 8 + gg]       = m0;
                        stage[(rowb + 8) * 8 + gg] = m1;
                    }
                }
            }
        }
        __syncthreads();

        // ---- coalesced write-out of this tile's group mins ----
        {
            const int row = tid >> 1, half = tid & 1;
            float4 v = *(float4*)&stage[row * 8 + half * 4];
            *(float4*)&g_hmin[(size_t)row * NHG + t * 8 + half * 4] = v;
        }

        // ---- convert prefetched fp32 -> bf16 buffer 1-p, ksq ----
        if (have_next) {
            asm volatile("cp.async.wait_group 0;" ::: "memory");
            __syncthreads();   // staging data visible to all
            const int row = tid >> 2, qtr = tid & 3;
            const int j = (t + GRID1) * KT + row;
            const float4* s = (const float4*)(smem + SM_ST32 + row * 256 + qtr * 64);
            char* dst = smem + (p ? SM_K0 : SM_K1) + row * TSTRIDE_B + qtr * 32;
            float ss = 0.f;
            uint2* d = (uint2*)dst;
            #pragma unroll
            for (int i = 0; i < 4; i++) {
                float4 v = s[i];
                ss = fmaf(v.x, v.x, ss); ss = fmaf(v.y, v.y, ss);
                ss = fmaf(v.z, v.z, ss); ss = fmaf(v.w, v.w, ss);
                __nv_bfloat162 p0 = __floats2bfloat162_rn(v.x, v.y);
                __nv_bfloat162 p1 = __floats2bfloat162_rn(v.z, v.w);
                uint2 u;
                u.x = *(uint32_t*)&p0;
                u.y = *(uint32_t*)&p1;
                d[i] = u;
            }
            ss += __shfl_xor_sync(0xFFFFFFFFu, ss, 1);
            ss += __shfl_xor_sync(0xFFFFFFFFu, ss, 2);
            if (qtr == 0)
                ((float*)(smem + (p ? SM_KSQ0 : SM_KSQ1)))[row] =
                    (j < NK) ? ss : CUDART_INF_F;
        }
        __syncthreads();
        p ^= 1;
    }
}

// ======================================================================
// Kernel 2 (fused): cutoff from group-mins -> compact -> exact fp32
//                   rescore -> exact top-8. grid NQ, 256 threads.
// ======================================================================
#define INS8T(s_, j_)                                                            \
    if ((s_) < l[7] || ((s_) == l[7] && (j_) < li[7])) {                         \
        l[7] = (s_); li[7] = (j_);                                               \
        _Pragma("unroll")                                                        \
        for (int u = 7; u > 0; u--)                                              \
            if (l[u] < l[u-1] || (l[u] == l[u-1] && li[u] < li[u-1])) {          \
                float ts = l[u]; l[u] = l[u-1]; l[u-1] = ts;                     \
                int ti = li[u]; li[u] = li[u-1]; li[u-1] = ti; }                 \
    }

#define INS1(s_)                                                                 \
    if ((s_) < l[7]) {                                                           \
        l[7] = (s_);                                                             \
        _Pragma("unroll")                                                        \
        for (int u = 7; u > 0; u--)                                              \
            if (l[u] < l[u-1]) { float ts = l[u]; l[u] = l[u-1]; l[u-1] = ts; }  \
    }

__global__ __launch_bounds__(256) void knn_select(
    const float* __restrict__ qm, const float* __restrict__ km)
{
    __shared__ float qs[64];
    __shared__ float ms[256 * 8];
    __shared__ int   mi[256 * 8];
    __shared__ int   s_list[CAP];
    __shared__ int   s_cnt;
    __shared__ float s_cut;
    const int q = blockIdx.x, tid = threadIdx.x;

    if (tid < 64) qs[tid] = qm[(size_t)q * DD + tid];
    if (tid == 0) s_cnt = 0;

    const float4* h4 = (const float4*)&g_hmin[(size_t)q * NHG];
    const int NV = NHG / 4;   // 782 float4

    // ---- phase A: per-thread top-8 of group-mins (float4 loads) ----
    float l[8];
    #pragma unroll
    for (int i = 0; i < 8; i++) l[i] = CUDART_INF_F;
    #pragma unroll
    for (int r = 0; r < 4; r++) {
        const int v4 = tid + r * 256;
        if (v4 < NV) {
            float4 v = h4[v4];
            INS1(v.x); INS1(v.y); INS1(v.z); INS1(v.w);
        }
    }
    #pragma unroll
    for (int m = 0; m < 8; m++) ms[tid * 8 + m] = l[m];

    for (int st = 128; st >= 1; st >>= 1) {
        __syncthreads();
        if (tid < st) {
            const int o = (tid + st) * 8;
            #pragma unroll 1
            for (int m = 0; m < 8; m++) {
                float s = ms[o + m];
                if (s >= l[7]) break;
                INS1(s);
            }
            #pragma unroll
            for (int m = 0; m < 8; m++) ms[tid * 8 + m] = l[m];
        }
    }
    if (tid == 0) s_cut = l[7] + MARGIN;
    __syncthreads();

    // ---- phase B: compact candidate 16-key groups (float4 loads) ----
    const float cut = s_cut;
    #pragma unroll
    for (int r = 0; r < 4; r++) {
        const int v4 = tid + r * 256;
        if (v4 < NV) {
            float4 v = h4[v4];
            if (v.x <= cut) { int p = atomicAdd(&s_cnt, 1); if (p < CAP) s_list[p] = v4 * 4; }
            if (v.y <= cut) { int p = atomicAdd(&s_cnt, 1); if (p < CAP) s_list[p] = v4 * 4 + 1; }
            if (v.z <= cut) { int p = atomicAdd(&s_cnt, 1); if (p < CAP) s_list[p] = v4 * 4 + 2; }
            if (v.w <= cut) { int p = atomicAdd(&s_cnt, 1); if (p < CAP) s_list[p] = v4 * 4 + 3; }
        }
    }
    __syncthreads();
    const int cnt = (s_cnt < CAP) ? s_cnt : CAP;

    // ---- phase C: exact fp32 rescore of cnt*16 keys ----
    int li[8];
    #pragma unroll
    for (int i = 0; i < 8; i++) { l[i] = CUDART_INF_F; li[i] = 0x7FFFFFFF; }

    const float4* qp = (const float4*)qs;
    for (int u = tid; u < cnt * GRP; u += 256) {
        const int j = s_list[u >> 4] * GRP + (u & 15);
        if (j < NK) {
            const float4* kp = (const float4*)(km + (size_t)j * DD);
            float dot = 0.f, ks = 0.f;
            #pragma unroll
            for (int w = 0; w < 16; w++) {
                float4 kv = kp[w];
                float4 qv = qp[w];
                dot = fmaf(kv.x, qv.x, dot); ks = fmaf(kv.x, kv.x, ks);
                dot = fmaf(kv.y, qv.y, dot); ks = fmaf(kv.y, kv.y, ks);
                dot = fmaf(kv.z, qv.z, dot); ks = fmaf(kv.z, kv.z, ks);
                dot = fmaf(kv.w, qv.w, dot); ks = fmaf(kv.w, kv.w, ks);
            }
            float s = fmaf(-2.f, dot, ks);
            INS8T(s, j);
        }
    }
    #pragma unroll
    for (int m = 0; m < 8; m++) { ms[tid * 8 + m] = l[m]; mi[tid * 8 + m] = li[m]; }

    for (int st = 128; st >= 1; st >>= 1) {
        __syncthreads();
        if (tid < st) {
            const int o = (tid + st) * 8;
            #pragma unroll 1
            for (int m = 0; m < 8; m++) {
                float s = ms[o + m];
                int   j = mi[o + m];
                bool better = (s < l[7]) || (s == l[7] && j < li[7]);
                if (!better) break;
                l[7] = s; li[7] = j;
                #pragma unroll
                for (int u = 7; u > 0; u--)
                    if (l[u] < l[u-1] || (l[u] == l[u-1] && li[u] < li[u-1])) {
                        float ts = l[u]; l[u] = l[u-1]; l[u-1] = ts;
                        int ti = li[u]; li[u] = li[u-1]; li[u-1] = ti;
                    }
            }
            #pragma unroll
            for (int m = 0; m < 8; m++) { ms[tid * 8 + m] = l[m]; mi[tid * 8 + m] = li[m]; }
        }
    }
    if (tid == 0) {
        #pragma unroll
        for (int m = 0; m < 8; m++) g_topidx[q * 8 + m] = li[m];
    }
}

// ======================================================================
// Kernel 3: gather obs[idx] -> out [8, 256, 3072]
// ======================================================================
__global__ __launch_bounds__(256) void knn_gather_kernel(
    const float* __restrict__ obs, float* __restrict__ out)
{
    const int b  = blockIdx.x;
    const int kk = b >> 8;
    const int q  = b & 255;
    const int src = g_topidx[q * 8 + kk];

    const float4* s = (const float4*)(obs + (size_t)src * OBS_ELEMS);
    float4*       d = (float4*)(out + ((size_t)kk * NQ + q) * OBS_ELEMS);

    #pragma unroll
    for (int i = threadIdx.x; i < OBS_ELEMS / 4; i += 256)
        d[i] = s[i];
}

// ======================================================================
extern "C" void kernel_launch(void* const* d_in, const int* in_sizes, int n_in,
                              void* d_out, int out_size)
{
    const float* q   = (const float*)d_in[0];
    const float* k   = (const float*)d_in[1];
    const float* obs = (const float*)d_in[2];
    float* out = (float*)d_out;

    cudaFuncSetAttribute(knn_score_min,
                         cudaFuncAttributeMaxDynamicSharedMemorySize, SM_TOTAL);

    knn_score_min<<<GRID1, 512, SM_TOTAL>>>(q, k);
    knn_select<<<NQ, 256>>>(q, k);
    knn_gather_kernel<<<NQ * 8, 256>>>(obs, out);
}